// round 16
// baseline (speedup 1.0000x reference)
#include <cuda_runtime.h>
#include <cuda_bf16.h>

#define BN_EPS 1e-5f
#define SC 0.17677669529663687f

// ---------------- scratch (device globals; no allocation allowed) -------------
__device__ float g_yv [2 * 256 * 4096];                 // v conv fp32 (for dw)
__device__ float g_pp [2 * 256 * 4096];                 // depthwise+BN
__device__ __nv_bfloat16 g_qk_hi[2 * 512 * 4096];
__device__ __nv_bfloat16 g_qk_lo[2 * 512 * 4096];
__device__ __nv_bfloat16 g_v_hi [2 * 256 * 4096];
__device__ __nv_bfloat16 g_v_lo [2 * 256 * 4096];
__device__ __nv_bfloat16 g_xh  [2 * 256 * 4096];        // x split
__device__ __nv_bfloat16 g_xl  [2 * 256 * 4096];
__device__ __nv_bfloat16 g_oph [2 * 256 * 4096];        // (o+pp) split (flash epi)
__device__ __nv_bfloat16 g_opl [2 * 256 * 4096];
__device__ __nv_bfloat16 g_wqkt_h[256 * 512], g_wqkt_l[256 * 512];   // [k][m]
__device__ __nv_bfloat16 g_wvt_h [256 * 256], g_wvt_l [256 * 256];
__device__ __nv_bfloat16 g_wprt_h[256 * 256], g_wprt_l[256 * 256];

__device__ __forceinline__ unsigned short bf_hi(float x) {
    return __bfloat16_as_ushort(__float2bfloat16(x));
}
__device__ __forceinline__ unsigned short bf_lo(float x, unsigned short h) {
    __nv_bfloat16 hb = __ushort_as_bfloat16(h);
    return __bfloat16_as_ushort(__float2bfloat16(x - __bfloat162float(hb)));
}
__device__ __forceinline__ unsigned pk(unsigned short a, unsigned short b) {
    return ((unsigned)b << 16) | (unsigned)a;
}
__device__ __forceinline__ unsigned smem_u32(const void* p) {
    unsigned a;
    asm("{ .reg .u64 t; cvta.to.shared.u64 t, %1; cvt.u32.u64 %0, t; }" : "=r"(a) : "l"(p));
    return a;
}
__device__ __forceinline__ void ldsm_x4(unsigned& r0, unsigned& r1, unsigned& r2, unsigned& r3,
                                        unsigned addr) {
    asm volatile("ldmatrix.sync.aligned.m8n8.x4.shared.b16 {%0,%1,%2,%3}, [%4];"
                 : "=r"(r0), "=r"(r1), "=r"(r2), "=r"(r3) : "r"(addr));
}
__device__ __forceinline__ void ldsm_x4t(unsigned& r0, unsigned& r1, unsigned& r2, unsigned& r3,
                                         unsigned addr) {
    asm volatile("ldmatrix.sync.aligned.m8n8.x4.trans.shared.b16 {%0,%1,%2,%3}, [%4];"
                 : "=r"(r0), "=r"(r1), "=r"(r2), "=r"(r3) : "r"(addr));
}
__device__ __forceinline__ void mma16816(float& c0, float& c1, float& c2, float& c3,
                                         unsigned a0, unsigned a1, unsigned a2, unsigned a3,
                                         unsigned b0, unsigned b1) {
    asm volatile(
        "mma.sync.aligned.m16n8k16.row.col.f32.bf16.bf16.f32 "
        "{%0,%1,%2,%3}, {%4,%5,%6,%7}, {%8,%9}, {%0,%1,%2,%3};"
        : "+f"(c0), "+f"(c1), "+f"(c2), "+f"(c3)
        : "r"(a0), "r"(a1), "r"(a2), "r"(a3), "r"(b0), "r"(b1));
}
__device__ __forceinline__ void cp_async16(unsigned dst, const void* src) {
    asm volatile("cp.async.cg.shared.global [%0], [%1], 16;" :: "r"(dst), "l"(src) : "memory");
}
__device__ __forceinline__ void cp_commit() {
    asm volatile("cp.async.commit_group;" ::: "memory");
}
__device__ __forceinline__ void cp_wait_all() {
    asm volatile("cp.async.wait_group 0;" ::: "memory");
}

// ---------------- prep kernels -------------------------------------------------
__global__ __launch_bounds__(256) void prep_split(
    const float* __restrict__ a, const float* __restrict__ b,
    __nv_bfloat16* __restrict__ h, __nv_bfloat16* __restrict__ l, int n)
{
    int i = (blockIdx.x * 256 + threadIdx.x) * 8;
    if (i >= n) return;
    float4 v0 = *reinterpret_cast<const float4*>(&a[i]);
    float4 v1 = *reinterpret_cast<const float4*>(&a[i + 4]);
    if (b) {
        float4 u0 = *reinterpret_cast<const float4*>(&b[i]);
        float4 u1 = *reinterpret_cast<const float4*>(&b[i + 4]);
        v0.x += u0.x; v0.y += u0.y; v0.z += u0.z; v0.w += u0.w;
        v1.x += u1.x; v1.y += u1.y; v1.z += u1.z; v1.w += u1.w;
    }
    float va[8] = {v0.x, v0.y, v0.z, v0.w, v1.x, v1.y, v1.z, v1.w};
    unsigned short hh[8], ll[8];
#pragma unroll
    for (int j = 0; j < 8; j++) { hh[j] = bf_hi(va[j]); ll[j] = bf_lo(va[j], hh[j]); }
    *reinterpret_cast<uint4*>(&h[i]) =
        make_uint4(pk(hh[0], hh[1]), pk(hh[2], hh[3]), pk(hh[4], hh[5]), pk(hh[6], hh[7]));
    *reinterpret_cast<uint4*>(&l[i]) =
        make_uint4(pk(ll[0], ll[1]), pk(ll[2], ll[3]), pk(ll[4], ll[5]), pk(ll[6], ll[7]));
}

__global__ __launch_bounds__(256) void prep_wt_all(
    const float* __restrict__ Wqk, const float* __restrict__ Wv,
    const float* __restrict__ Wpr)
{
    int idx = blockIdx.x * 256 + threadIdx.x;
    const float* W; __nv_bfloat16 *th, *tl; int M, sc_rows, off;
    if (idx < 131072)      { W = Wqk; th = g_wqkt_h; tl = g_wqkt_l; M = 512; sc_rows = 256; off = idx; }
    else if (idx < 196608) { W = Wv;  th = g_wvt_h;  tl = g_wvt_l;  M = 256; sc_rows = 0;   off = idx - 131072; }
    else                   { W = Wpr; th = g_wprt_h; tl = g_wprt_l; M = 256; sc_rows = 0;   off = idx - 196608; }
    int k = off / M, m = off - k * M;
    float v = W[m * 256 + k];
    if (m < sc_rows) v *= SC;
    unsigned short h = bf_hi(v);
    th[off] = __ushort_as_bfloat16(h);
    tl[off] = __ushort_as_bfloat16(bf_lo(v, h));
}

// =============== all-bf16 conv1x1 + BN core (cp.async pipelined) ==============
#define BW_L 4608
#define BX_H 9216
#define BX_L 17920
#define BUFB 26624
#define CB_SMEM (2 * BUFB)

__device__ __forceinline__ void conv_core(
    char* csm,
    const __nv_bfloat16* __restrict__ Wth, const __nv_bfloat16* __restrict__ Wtl,
    const __nv_bfloat16* __restrict__ Xh, const __nv_bfloat16* __restrict__ Xl,
    float* __restrict__ dout,
    const float* __restrict__ gg, const float* __restrict__ bb,
    const float* __restrict__ mm, const float* __restrict__ vv,
    int M, int out_mode, int b, int m0, int n0)
{
    const unsigned sbc = smem_u32(csm);
    const int N = 4096;
    const int t = threadIdx.x, lane = t & 31, w = t >> 5;

    auto chunk_copy = [&](unsigned base, int k0) {
#pragma unroll
        for (int c = t; c < 1536; c += 128) {
            if (c < 512) {
                int arr = c >> 8, rem = c & 255, r = rem >> 3, c16 = rem & 7;
                const __nv_bfloat16* s = (arr ? Wtl : Wth) + (k0 + r) * M + m0 + c16 * 8;
                cp_async16(base + arr * BW_L + r * 144 + c16 * 16, s);
            } else {
                int c2 = c - 512;
                int arr = c2 >> 9, rem = c2 & 511, r = rem >> 4, c16 = rem & 15;
                const __nv_bfloat16* s = (arr ? Xl : Xh) + (k0 + r) * N + n0 + c16 * 8;
                cp_async16(base + BX_H + arr * (BX_L - BX_H) + r * 272 + c16 * 16, s);
            }
        }
        cp_commit();
    };

    chunk_copy(sbc, 0);

    float S[16][4];
#pragma unroll
    for (int j = 0; j < 16; j++)
#pragma unroll
        for (int c = 0; c < 4; c++) S[j][c] = 0.f;

    for (int c0 = 0; c0 < 8; c0++) {
        cp_wait_all();
        __syncthreads();
        if (c0 < 7) chunk_copy(sbc + ((c0 + 1) & 1) * BUFB, (c0 + 1) * 32);
        const unsigned bbuf = sbc + (c0 & 1) * BUFB;

        unsigned wa_[2][2][4];
#pragma unroll
        for (int sp = 0; sp < 2; sp++)
#pragma unroll
            for (int s = 0; s < 2; s++) {
                unsigned drow = s * 16 + ((lane >> 4) & 1) * 8 + (lane & 7);
                unsigned col  = (unsigned)w * 32 + ((lane >> 3) & 1) * 16;
                ldsm_x4t(wa_[sp][s][0], wa_[sp][s][1], wa_[sp][s][2], wa_[sp][s][3],
                         bbuf + sp * BW_L + drow * 144 + col);
            }
#pragma unroll
        for (int j = 0; j < 16; j++) {
            unsigned xh0, xh1, xh2, xh3, xl0, xl1, xl2, xl3;
            ldsm_x4t(xh0, xh1, xh2, xh3, bbuf + BX_H + lane * 272 + j * 16);
            ldsm_x4t(xl0, xl1, xl2, xl3, bbuf + BX_L + lane * 272 + j * 16);
            mma16816(S[j][0], S[j][1], S[j][2], S[j][3],
                     wa_[0][0][0], wa_[0][0][1], wa_[0][0][2], wa_[0][0][3], xh0, xh1);
            mma16816(S[j][0], S[j][1], S[j][2], S[j][3],
                     wa_[0][1][0], wa_[0][1][1], wa_[0][1][2], wa_[0][1][3], xh2, xh3);
            mma16816(S[j][0], S[j][1], S[j][2], S[j][3],
                     wa_[0][0][0], wa_[0][0][1], wa_[0][0][2], wa_[0][0][3], xl0, xl1);
            mma16816(S[j][0], S[j][1], S[j][2], S[j][3],
                     wa_[0][1][0], wa_[0][1][1], wa_[0][1][2], wa_[0][1][3], xl2, xl3);
            mma16816(S[j][0], S[j][1], S[j][2], S[j][3],
                     wa_[1][0][0], wa_[1][0][1], wa_[1][0][2], wa_[1][0][3], xh0, xh1);
            mma16816(S[j][0], S[j][1], S[j][2], S[j][3],
                     wa_[1][1][0], wa_[1][1][1], wa_[1][1][2], wa_[1][1][3], xh2, xh3);
        }
    }

    const int r0 = m0 + w * 16 + (lane >> 2);
    const int r1 = r0 + 8;
    float s0 = gg[r0] * rsqrtf(vv[r0] + BN_EPS);
    float bi0 = bb[r0] - mm[r0] * s0;
    float s1 = gg[r1] * rsqrtf(vv[r1] + BN_EPS);
    float bi1 = bb[r1] - mm[r1] * s1;
    if (out_mode == 0 && r0 < 256) { bi0 *= SC; }
    if (out_mode == 0 && r1 < 256) { bi1 *= SC; }

#pragma unroll
    for (int j = 0; j < 16; j++) {
        int n = n0 + j * 8 + (lane & 3) * 2;
        float o0 = S[j][0] * s0 + bi0, o1 = S[j][1] * s0 + bi0;
        float o2 = S[j][2] * s1 + bi1, o3 = S[j][3] * s1 + bi1;
        long i0 = (long)b * M * 4096 + (long)r0 * 4096 + n;
        long i1 = (long)b * M * 4096 + (long)r1 * 4096 + n;
        if (out_mode == 2) {
            *reinterpret_cast<float2*>(&dout[i0]) = make_float2(o0, o1);
            *reinterpret_cast<float2*>(&dout[i1]) = make_float2(o2, o3);
        } else {
            if (out_mode == 1) {
                *reinterpret_cast<float2*>(&g_yv[i0]) = make_float2(o0, o1);
                *reinterpret_cast<float2*>(&g_yv[i1]) = make_float2(o2, o3);
            }
            __nv_bfloat16* H = (out_mode == 0 ? g_qk_hi : g_v_hi);
            __nv_bfloat16* L = (out_mode == 0 ? g_qk_lo : g_v_lo);
            unsigned short h0 = bf_hi(o0), h1 = bf_hi(o1);
            unsigned short h2 = bf_hi(o2), h3 = bf_hi(o3);
            *reinterpret_cast<unsigned*>(&H[i0]) = pk(h0, h1);
            *reinterpret_cast<unsigned*>(&H[i1]) = pk(h2, h3);
            *reinterpret_cast<unsigned*>(&L[i0]) = pk(bf_lo(o0, h0), bf_lo(o1, h1));
            *reinterpret_cast<unsigned*>(&L[i1]) = pk(bf_lo(o2, h2), bf_lo(o3, h3));
        }
    }
}

// ---------------- depthwise 5x5 core (128 threads, smem from caller) ----------
__device__ __forceinline__ void dw5_core(
    char* csm, int bc,
    const float* __restrict__ w_pe,
    const float* __restrict__ gg, const float* __restrict__ bb,
    const float* __restrict__ mm, const float* __restrict__ vv)
{
    const int c = bc & 255;
    const float* src = g_yv + bc * 4096;
    float* dst = g_pp + bc * 4096;
    float (*tile)[68] = reinterpret_cast<float(*)[68]>(csm);
    float* wk = reinterpret_cast<float*>(csm + 68 * 68 * 4);
    const int t = threadIdx.x;   // 0..127

    for (int i = t * 4; i < 68 * 68; i += 512)
        *reinterpret_cast<float4*>(&((float*)tile)[i]) = make_float4(0.f, 0.f, 0.f, 0.f);
    if (t < 25) wk[t] = w_pe[c * 25 + t];
    __syncthreads();
    for (int i = t * 4; i < 4096; i += 512) {
        float4 v = *reinterpret_cast<const float4*>(&src[i]);
        int y = (i >> 6) + 2, x = (i & 63) + 2;
        tile[y][x] = v.x; tile[y][x + 1] = v.y; tile[y][x + 2] = v.z; tile[y][x + 3] = v.w;
    }
    __syncthreads();

    float s  = gg[c] * rsqrtf(vv[c] + BN_EPS);
    float bi = bb[c] - mm[c] * s;

    for (int i = t * 4; i < 4096; i += 512) {
        int y = i >> 6, x = i & 63;
        float a0 = 0.f, a1 = 0.f, a2 = 0.f, a3 = 0.f;
#pragma unroll
        for (int ky = 0; ky < 5; ky++)
#pragma unroll
            for (int kx = 0; kx < 5; kx++) {
                float wv = wk[ky * 5 + kx];
                a0 = fmaf(tile[y + ky][x + kx],     wv, a0);
                a1 = fmaf(tile[y + ky][x + kx + 1], wv, a1);
                a2 = fmaf(tile[y + ky][x + kx + 2], wv, a2);
                a3 = fmaf(tile[y + ky][x + kx + 3], wv, a3);
            }
        *reinterpret_cast<float4*>(&dst[i]) =
            make_float4(a0 * s + bi, a1 * s + bi, a2 * s + bi, a3 * s + bi);
    }
}

// ---------------- v conv alone -------------------------------------------------
__global__ __launch_bounds__(128) void conv_v_p(
    const float* __restrict__ v_g, const float* __restrict__ v_b,
    const float* __restrict__ v_m, const float* __restrict__ v_v)
{
    extern __shared__ char csm[];
    const int b = blockIdx.z;
    conv_core(csm, g_wvt_h, g_wvt_l,
              g_xh + b * 256 * 4096, g_xl + b * 256 * 4096, nullptr,
              v_g, v_b, v_m, v_v, 256, 1, b, blockIdx.y * 64, blockIdx.x * 128);
}

// ---------------- fused qk conv + depthwise (co-scheduled grid) ---------------
// y in [0,8): qk conv m-job y.   y in [8,16): dw slice -> bc = z*256 + (y-8)*32 + x
__global__ __launch_bounds__(128) void conv_qk_dw(
    const float* __restrict__ qk_g, const float* __restrict__ qk_b,
    const float* __restrict__ qk_m, const float* __restrict__ qk_v,
    const float* __restrict__ w_pe,
    const float* __restrict__ pe_g, const float* __restrict__ pe_b,
    const float* __restrict__ pe_m, const float* __restrict__ pe_v)
{
    extern __shared__ char csm[];
    const int b = blockIdx.z;
    if (blockIdx.y < 8) {
        conv_core(csm, g_wqkt_h, g_wqkt_l,
                  g_xh + b * 256 * 4096, g_xl + b * 256 * 4096, nullptr,
                  qk_g, qk_b, qk_m, qk_v, 512, 0, b, blockIdx.y * 64, blockIdx.x * 128);
    } else {
        int bc = b * 256 + (blockIdx.y - 8) * 32 + blockIdx.x;
        dw5_core(csm, bc, w_pe, pe_g, pe_b, pe_m, pe_v);
    }
}

__global__ __launch_bounds__(128) void conv_proj(
    float* __restrict__ dout,
    const float* __restrict__ pr_g, const float* __restrict__ pr_b,
    const float* __restrict__ pr_m, const float* __restrict__ pr_v)
{
    extern __shared__ char csm[];
    const int b = blockIdx.z;
    conv_core(csm, g_wprt_h, g_wprt_l,
              g_oph + b * 256 * 4096, g_opl + b * 256 * 4096, dout,
              pr_g, pr_b, pr_m, pr_v, 256, 2, b, blockIdx.y * 64, blockIdx.x * 128);
}

// ================= flash attention (unchanged from R14/R15 WIN) ===============
#define TS 272
#define BUFSZ  34816
#define FM_SMEM (2 * BUFSZ)

__device__ __forceinline__ void kv_copy(unsigned base, int t,
    const __nv_bfloat16* Kh, const __nv_bfloat16* Kl,
    const __nv_bfloat16* Vh, const __nv_bfloat16* Vl, int m0)
{
#pragma unroll
    for (int c = t; c < 2048; c += 128) {
        int arr = c >> 9, d = (c >> 4) & 31, mb = c & 15;
        const __nv_bfloat16* s =
            (arr == 0 ? Kh : (arr == 1 ? Kl : (arr == 2 ? Vh : Vl))) + d * 4096 + m0 + mb * 8;
        cp_async16(base + arr * 8704 + d * TS + mb * 16, s);
    }
    cp_commit();
}

__global__ __launch_bounds__(128, 3) void flash_mma()
{
    extern __shared__ char smbuf[];
    const unsigned sb = smem_u32(smbuf);
    const int t = threadIdx.x, lane = t & 31, w = t >> 5;

    const int bh = blockIdx.y;
    const int b = bh >> 5, area = (bh >> 3) & 3, h = bh & 7;
    const int q0 = blockIdx.x * 64;

    const int qch = (b * 512 + h * 32) * 4096 + area * 1024;
    const int kch = (b * 512 + 256 + h * 32) * 4096 + area * 1024;
    const int vch = (b * 256 + h * 32) * 4096 + area * 1024;
    const __nv_bfloat16* Qh = g_qk_hi + qch + q0;
    const __nv_bfloat16* Ql = g_qk_lo + qch + q0;
    const __nv_bfloat16* Kh = g_qk_hi + kch;
    const __nv_bfloat16* Kl = g_qk_lo + kch;
    const __nv_bfloat16* Vh = g_v_hi + vch;
    const __nv_bfloat16* Vl = g_v_lo + vch;

#pragma unroll
    for (int c = t; c < 512; c += 128) {
        int arr = c >> 8, d = (c >> 3) & 31, qb = c & 7;
        const __nv_bfloat16* s = (arr ? Ql : Qh) + d * 4096 + qb * 8;
        *reinterpret_cast<uint4*>(smbuf + arr * 8704 + d * TS + qb * 16) =
            *reinterpret_cast<const uint4*>(s);
    }
    __syncthreads();

    unsigned qa[2][2][4];
#pragma unroll
    for (int sp = 0; sp < 2; sp++)
#pragma unroll
        for (int s = 0; s < 2; s++) {
            unsigned drow = s * 16 + ((lane >> 4) & 1) * 8 + (lane & 7);
            unsigned col  = (unsigned)w * 32 + ((lane >> 3) & 1) * 16;
            ldsm_x4t(qa[sp][s][0], qa[sp][s][1], qa[sp][s][2], qa[sp][s][3],
                     sb + sp * 8704 + drow * TS + col);
        }
    __syncthreads();

    kv_copy(sb, t, Kh, Kl, Vh, Vl, 0);

    float Oacc[4][4];
#pragma unroll
    for (int dn = 0; dn < 4; dn++)
#pragma unroll
        for (int c = 0; c < 4; c++) Oacc[dn][c] = 0.f;
    float mr0 = -1e30f, mr1 = -1e30f, lr0 = 0.f, lr1 = 0.f;

    for (int kt = 0; kt < 8; kt++) {
        cp_wait_all();
        __syncthreads();
        if (kt < 7)
            kv_copy(sb + ((kt + 1) & 1) * BUFSZ, t, Kh, Kl, Vh, Vl, (kt + 1) * 128);
        const unsigned kb = sb + (kt & 1) * BUFSZ;

        float S[16][4];
#pragma unroll
        for (int j = 0; j < 16; j++) {
            unsigned kh0, kh1, kh2, kh3, kl0, kl1, kl2, kl3;
            ldsm_x4t(kh0, kh1, kh2, kh3, kb + lane * TS + j * 16);
            ldsm_x4t(kl0, kl1, kl2, kl3, kb + 8704 + lane * TS + j * 16);
            float a0 = 0.f, a1 = 0.f, a2 = 0.f, a3 = 0.f;
            float b0 = 0.f, b1 = 0.f, b2 = 0.f, b3 = 0.f;
            mma16816(a0, a1, a2, a3, qa[0][0][0], qa[0][0][1], qa[0][0][2], qa[0][0][3], kh0, kh1);
            mma16816(a0, a1, a2, a3, qa[0][1][0], qa[0][1][1], qa[0][1][2], qa[0][1][3], kh2, kh3);
            mma16816(b0, b1, b2, b3, qa[0][0][0], qa[0][0][1], qa[0][0][2], qa[0][0][3], kl0, kl1);
            mma16816(b0, b1, b2, b3, qa[0][1][0], qa[0][1][1], qa[0][1][2], qa[0][1][3], kl2, kl3);
            mma16816(b0, b1, b2, b3, qa[1][0][0], qa[1][0][1], qa[1][0][2], qa[1][0][3], kh0, kh1);
            mma16816(b0, b1, b2, b3, qa[1][1][0], qa[1][1][1], qa[1][1][2], qa[1][1][3], kh2, kh3);
            S[j][0] = a0 + b0; S[j][1] = a1 + b1; S[j][2] = a2 + b2; S[j][3] = a3 + b3;
        }

        float mx0 = -1e30f, mx1 = -1e30f;
#pragma unroll
        for (int j = 0; j < 16; j++) {
            mx0 = fmaxf(mx0, fmaxf(S[j][0], S[j][1]));
            mx1 = fmaxf(mx1, fmaxf(S[j][2], S[j][3]));
        }
        mx0 = fmaxf(mx0, __shfl_xor_sync(0xFFFFFFFFu, mx0, 1));
        mx0 = fmaxf(mx0, __shfl_xor_sync(0xFFFFFFFFu, mx0, 2));
        mx1 = fmaxf(mx1, __shfl_xor_sync(0xFFFFFFFFu, mx1, 1));
        mx1 = fmaxf(mx1, __shfl_xor_sync(0xFFFFFFFFu, mx1, 2));
        float nm0 = fmaxf(mr0, mx0), nm1 = fmaxf(mr1, mx1);
        float be0 = __expf(mr0 - nm0), be1 = __expf(mr1 - nm1);
        float lt0 = 0.f, lt1 = 0.f;
#pragma unroll
        for (int j = 0; j < 16; j++) {
            S[j][0] = __expf(S[j][0] - nm0); lt0 += S[j][0];
            S[j][1] = __expf(S[j][1] - nm0); lt0 += S[j][1];
            S[j][2] = __expf(S[j][2] - nm1); lt1 += S[j][2];
            S[j][3] = __expf(S[j][3] - nm1); lt1 += S[j][3];
        }
        lt0 += __shfl_xor_sync(0xFFFFFFFFu, lt0, 1);
        lt0 += __shfl_xor_sync(0xFFFFFFFFu, lt0, 2);
        lt1 += __shfl_xor_sync(0xFFFFFFFFu, lt1, 1);
        lt1 += __shfl_xor_sync(0xFFFFFFFFu, lt1, 2);
        lr0 = lr0 * be0 + lt0; lr1 = lr1 * be1 + lt1;
        mr0 = nm0; mr1 = nm1;
#pragma unroll
        for (int dn = 0; dn < 4; dn++) {
            Oacc[dn][0] *= be0; Oacc[dn][1] *= be0;
            Oacc[dn][2] *= be1; Oacc[dn][3] *= be1;
        }

#pragma unroll
        for (int tt = 0; tt < 8; tt++) {
            unsigned ah[4], al[4];
            {
                unsigned short h0 = bf_hi(S[2*tt][0]),   h1 = bf_hi(S[2*tt][1]);
                unsigned short h2 = bf_hi(S[2*tt][2]),   h3 = bf_hi(S[2*tt][3]);
                unsigned short h4 = bf_hi(S[2*tt+1][0]), h5 = bf_hi(S[2*tt+1][1]);
                unsigned short h6 = bf_hi(S[2*tt+1][2]), h7 = bf_hi(S[2*tt+1][3]);
                ah[0] = pk(h0, h1); ah[1] = pk(h2, h3);
                ah[2] = pk(h4, h5); ah[3] = pk(h6, h7);
                al[0] = pk(bf_lo(S[2*tt][0], h0),   bf_lo(S[2*tt][1], h1));
                al[1] = pk(bf_lo(S[2*tt][2], h2),   bf_lo(S[2*tt][3], h3));
                al[2] = pk(bf_lo(S[2*tt+1][0], h4), bf_lo(S[2*tt+1][1], h5));
                al[3] = pk(bf_lo(S[2*tt+1][2], h6), bf_lo(S[2*tt+1][3], h7));
            }
#pragma unroll
            for (int p = 0; p < 2; p++) {
                unsigned drow = (unsigned)p * 16 + ((lane >> 4) & 1) * 8 + (lane & 7);
                unsigned colb = (unsigned)tt * 32 + ((lane >> 3) & 1) * 16;
                unsigned vh0, vh1, vh2, vh3, vl0, vl1, vl2, vl3;
                ldsm_x4(vh0, vh1, vh2, vh3, kb + 17408 + drow * TS + colb);
                ldsm_x4(vl0, vl1, vl2, vl3, kb + 26112 + drow * TS + colb);
                int d0 = p * 2, d1 = p * 2 + 1;
                mma16816(Oacc[d0][0], Oacc[d0][1], Oacc[d0][2], Oacc[d0][3],
                         ah[0], ah[1], ah[2], ah[3], vh0, vh1);
                mma16816(Oacc[d0][0], Oacc[d0][1], Oacc[d0][2], Oacc[d0][3],
                         ah[0], ah[1], ah[2], ah[3], vl0, vl1);
                mma16816(Oacc[d0][0], Oacc[d0][1], Oacc[d0][2], Oacc[d0][3],
                         al[0], al[1], al[2], al[3], vh0, vh1);
                mma16816(Oacc[d1][0], Oacc[d1][1], Oacc[d1][2], Oacc[d1][3],
                         ah[0], ah[1], ah[2], ah[3], vh2, vh3);
                mma16816(Oacc[d1][0], Oacc[d1][1], Oacc[d1][2], Oacc[d1][3],
                         ah[0], ah[1], ah[2], ah[3], vl2, vl3);
                mma16816(Oacc[d1][0], Oacc[d1][1], Oacc[d1][2], Oacc[d1][3],
                         al[0], al[1], al[2], al[3], vh2, vh3);
            }
        }
    }

    __syncthreads();
    {
        float inv0 = 1.f / lr0, inv1 = 1.f / lr1;
        int r = w * 16 + (lane >> 2);
        int dc = (lane & 3) * 2;
        float* Os = (float*)(smbuf);
#pragma unroll
        for (int dn = 0; dn < 4; dn++) {
            int d = dn * 8 + dc;
            Os[r * 33 + d]           = Oacc[dn][0] * inv0;
            Os[r * 33 + d + 1]       = Oacc[dn][1] * inv0;
            Os[(r + 8) * 33 + d]     = Oacc[dn][2] * inv1;
            Os[(r + 8) * 33 + d + 1] = Oacc[dn][3] * inv1;
        }
    }
    __syncthreads();

    const long ob = (long)(b * 256 + h * 32) * 4096 + area * 1024 + q0;
    const float* Pp = g_pp + ob;
    __nv_bfloat16* OH = g_oph + ob;
    __nv_bfloat16* OL = g_opl + ob;
    const float* Os = (const float*)(smbuf);
    for (int i = t * 4; i < 2048; i += 512) {
        int d = i >> 6, q = i & 63;
        float o[4];
        o[0] = Os[(q + 0) * 33 + d];
        o[1] = Os[(q + 1) * 33 + d];
        o[2] = Os[(q + 2) * 33 + d];
        o[3] = Os[(q + 3) * 33 + d];
        float4 p = *reinterpret_cast<const float4*>(&Pp[d * 4096 + q]);
        o[0] += p.x; o[1] += p.y; o[2] += p.z; o[3] += p.w;
        unsigned short hh[4], ll[4];
#pragma unroll
        for (int j = 0; j < 4; j++) { hh[j] = bf_hi(o[j]); ll[j] = bf_lo(o[j], hh[j]); }
        *reinterpret_cast<uint2*>(&OH[d * 4096 + q]) =
            make_uint2(pk(hh[0], hh[1]), pk(hh[2], hh[3]));
        *reinterpret_cast<uint2*>(&OL[d * 4096 + q]) =
            make_uint2(pk(ll[0], ll[1]), pk(ll[2], ll[3]));
    }
}

// ---------------- launch ------------------------------------------------------
extern "C" void kernel_launch(void* const* d_in, const int* in_sizes, int n_in,
                              void* d_out, int out_size)
{
    const float *x, *w_qk, *w_v, *w_pe, *w_proj;
    const float *qk_g, *qk_b, *qk_m, *qk_v;
    const float *v_g, *v_b, *v_m, *v_v;
    const float *pe_g, *pe_b, *pe_m, *pe_v;
    const float *pr_g, *pr_b, *pr_m, *pr_v;

    x = (const float*)d_in[0];
    w_qk = (const float*)d_in[1];
    if (in_sizes[2] == 512) {
        qk_g = (const float*)d_in[2];  qk_b = (const float*)d_in[3];
        qk_m = (const float*)d_in[4];  qk_v = (const float*)d_in[5];
        w_v  = (const float*)d_in[6];
        v_g  = (const float*)d_in[7];  v_b  = (const float*)d_in[8];
        v_m  = (const float*)d_in[9];  v_v  = (const float*)d_in[10];
        w_pe = (const float*)d_in[11];
        pe_g = (const float*)d_in[12]; pe_b = (const float*)d_in[13];
        pe_m = (const float*)d_in[14]; pe_v = (const float*)d_in[15];
        w_proj = (const float*)d_in[16];
        pr_g = (const float*)d_in[17]; pr_b = (const float*)d_in[18];
        pr_m = (const float*)d_in[19]; pr_v = (const float*)d_in[20];
    } else {
        w_v    = (const float*)d_in[2];
        w_pe   = (const float*)d_in[3];
        w_proj = (const float*)d_in[4];
        qk_g = (const float*)d_in[5];  qk_b = (const float*)d_in[6];
        qk_m = (const float*)d_in[7];  qk_v = (const float*)d_in[8];
        v_g  = (const float*)d_in[9];  v_b  = (const float*)d_in[10];
        v_m  = (const float*)d_in[11]; v_v  = (const float*)d_in[12];
        pe_g = (const float*)d_in[13]; pe_b = (const float*)d_in[14];
        pe_m = (const float*)d_in[15]; pe_v = (const float*)d_in[16];
        pr_g = (const float*)d_in[17]; pr_b = (const float*)d_in[18];
        pr_m = (const float*)d_in[19]; pr_v = (const float*)d_in[20];
    }
    float* out = (float*)d_out;

    static __nv_bfloat16* p_xh = nullptr;
    static __nv_bfloat16* p_xl = nullptr;
    if (!p_xh) {
        void* p;
        cudaGetSymbolAddress(&p, g_xh); p_xh = (__nv_bfloat16*)p;
        cudaGetSymbolAddress(&p, g_xl); p_xl = (__nv_bfloat16*)p;
    }

    cudaFuncSetAttribute(flash_mma, cudaFuncAttributeMaxDynamicSharedMemorySize, FM_SMEM);
    cudaFuncSetAttribute(conv_v_p, cudaFuncAttributeMaxDynamicSharedMemorySize, CB_SMEM);
    cudaFuncSetAttribute(conv_qk_dw, cudaFuncAttributeMaxDynamicSharedMemorySize, CB_SMEM);
    cudaFuncSetAttribute(conv_proj, cudaFuncAttributeMaxDynamicSharedMemorySize, CB_SMEM);

    const int NX = 2 * 256 * 4096;
    prep_wt_all<<<1024, 256>>>(w_qk, w_v, w_proj);
    prep_split<<<NX / 2048, 256>>>(x, nullptr, p_xh, p_xl, NX);

    // 1. v conv first (dw depends on it)
    conv_v_p<<<dim3(32, 4, 2), 128, CB_SMEM>>>(v_g, v_b, v_m, v_v);
    // 2. qk conv co-scheduled with depthwise (dw fills qk's tail)
    conv_qk_dw<<<dim3(32, 16, 2), 128, CB_SMEM>>>(qk_g, qk_b, qk_m, qk_v,
                                                  w_pe, pe_g, pe_b, pe_m, pe_v);
    // 3. flash attention (epilogue fuses +pp and bf16 split)
    flash_mma<<<dim3(16, 64), 128, FM_SMEM>>>();
    // 4. projection conv
    conv_proj<<<dim3(32, 4, 2), 128, CB_SMEM>>>(out, pr_g, pr_b, pr_m, pr_v);
}

// round 17
// speedup vs baseline: 1.0465x; 1.0465x over previous
#include <cuda_runtime.h>
#include <cuda_bf16.h>

#define BN_EPS 1e-5f
#define SC 0.17677669529663687f

// ---------------- scratch (device globals; no allocation allowed) -------------
__device__ float g_yv [2 * 256 * 4096];                 // v conv fp32 (for dw)
__device__ float g_pp [2 * 256 * 4096];                 // depthwise+BN
__device__ __nv_bfloat16 g_qk_hi[2 * 512 * 4096];
__device__ __nv_bfloat16 g_qk_lo[2 * 512 * 4096];
__device__ __nv_bfloat16 g_v_hi [2 * 256 * 4096];
__device__ __nv_bfloat16 g_v_lo [2 * 256 * 4096];
__device__ __nv_bfloat16 g_xh  [2 * 256 * 4096];        // x split
__device__ __nv_bfloat16 g_xl  [2 * 256 * 4096];
__device__ __nv_bfloat16 g_oph [2 * 256 * 4096];        // (o+pp) split (flash epi)
__device__ __nv_bfloat16 g_opl [2 * 256 * 4096];
__device__ __nv_bfloat16 g_wqkt_h[256 * 512], g_wqkt_l[256 * 512];   // [k][m]
__device__ __nv_bfloat16 g_wvt_h [256 * 256], g_wvt_l [256 * 256];
__device__ __nv_bfloat16 g_wprt_h[256 * 256], g_wprt_l[256 * 256];

__device__ __forceinline__ unsigned short bf_hi(float x) {
    return __bfloat16_as_ushort(__float2bfloat16(x));
}
__device__ __forceinline__ unsigned short bf_lo(float x, unsigned short h) {
    __nv_bfloat16 hb = __ushort_as_bfloat16(h);
    return __bfloat16_as_ushort(__float2bfloat16(x - __bfloat162float(hb)));
}
__device__ __forceinline__ unsigned pk(unsigned short a, unsigned short b) {
    return ((unsigned)b << 16) | (unsigned)a;
}
__device__ __forceinline__ unsigned smem_u32(const void* p) {
    unsigned a;
    asm("{ .reg .u64 t; cvta.to.shared.u64 t, %1; cvt.u32.u64 %0, t; }" : "=r"(a) : "l"(p));
    return a;
}
__device__ __forceinline__ void ldsm_x4(unsigned& r0, unsigned& r1, unsigned& r2, unsigned& r3,
                                        unsigned addr) {
    asm volatile("ldmatrix.sync.aligned.m8n8.x4.shared.b16 {%0,%1,%2,%3}, [%4];"
                 : "=r"(r0), "=r"(r1), "=r"(r2), "=r"(r3) : "r"(addr));
}
__device__ __forceinline__ void ldsm_x4t(unsigned& r0, unsigned& r1, unsigned& r2, unsigned& r3,
                                         unsigned addr) {
    asm volatile("ldmatrix.sync.aligned.m8n8.x4.trans.shared.b16 {%0,%1,%2,%3}, [%4];"
                 : "=r"(r0), "=r"(r1), "=r"(r2), "=r"(r3) : "r"(addr));
}
__device__ __forceinline__ void mma16816(float& c0, float& c1, float& c2, float& c3,
                                         unsigned a0, unsigned a1, unsigned a2, unsigned a3,
                                         unsigned b0, unsigned b1) {
    asm volatile(
        "mma.sync.aligned.m16n8k16.row.col.f32.bf16.bf16.f32 "
        "{%0,%1,%2,%3}, {%4,%5,%6,%7}, {%8,%9}, {%0,%1,%2,%3};"
        : "+f"(c0), "+f"(c1), "+f"(c2), "+f"(c3)
        : "r"(a0), "r"(a1), "r"(a2), "r"(a3), "r"(b0), "r"(b1));
}
__device__ __forceinline__ void cp_async16(unsigned dst, const void* src) {
    asm volatile("cp.async.cg.shared.global [%0], [%1], 16;" :: "r"(dst), "l"(src) : "memory");
}
__device__ __forceinline__ void cp_commit() {
    asm volatile("cp.async.commit_group;" ::: "memory");
}
__device__ __forceinline__ void cp_wait_all() {
    asm volatile("cp.async.wait_group 0;" ::: "memory");
}

// ---------------- fused prep: weights (blocks<1024) + x split (blocks>=1024) ---
__global__ __launch_bounds__(256) void prep_all(
    const float* __restrict__ Wqk, const float* __restrict__ Wv,
    const float* __restrict__ Wpr, const float* __restrict__ x)
{
    if (blockIdx.x < 1024) {
        int idx = blockIdx.x * 256 + threadIdx.x;
        const float* W; __nv_bfloat16 *th, *tl; int M, sc_rows, off;
        if (idx < 131072)      { W = Wqk; th = g_wqkt_h; tl = g_wqkt_l; M = 512; sc_rows = 256; off = idx; }
        else if (idx < 196608) { W = Wv;  th = g_wvt_h;  tl = g_wvt_l;  M = 256; sc_rows = 0;   off = idx - 131072; }
        else                   { W = Wpr; th = g_wprt_h; tl = g_wprt_l; M = 256; sc_rows = 0;   off = idx - 196608; }
        int k = off / M, m = off - k * M;
        float v = W[m * 256 + k];
        if (m < sc_rows) v *= SC;
        unsigned short h = bf_hi(v);
        th[off] = __ushort_as_bfloat16(h);
        tl[off] = __ushort_as_bfloat16(bf_lo(v, h));
    } else {
        int i = ((blockIdx.x - 1024) * 256 + threadIdx.x) * 8;   // < 2*256*4096
        float4 v0 = *reinterpret_cast<const float4*>(&x[i]);
        float4 v1 = *reinterpret_cast<const float4*>(&x[i + 4]);
        float va[8] = {v0.x, v0.y, v0.z, v0.w, v1.x, v1.y, v1.z, v1.w};
        unsigned short hh[8], ll[8];
#pragma unroll
        for (int j = 0; j < 8; j++) { hh[j] = bf_hi(va[j]); ll[j] = bf_lo(va[j], hh[j]); }
        *reinterpret_cast<uint4*>(&g_xh[i]) =
            make_uint4(pk(hh[0], hh[1]), pk(hh[2], hh[3]), pk(hh[4], hh[5]), pk(hh[6], hh[7]));
        *reinterpret_cast<uint4*>(&g_xl[i]) =
            make_uint4(pk(ll[0], ll[1]), pk(ll[2], ll[3]), pk(ll[4], ll[5]), pk(ll[6], ll[7]));
    }
}

// =============== all-bf16 conv1x1 + BN core (cp.async pipelined) ==============
#define BW_L 4608
#define BX_H 9216
#define BX_L 17920
#define BUFB 26624
#define CB_SMEM (2 * BUFB)

__device__ __forceinline__ void conv_core(
    char* csm,
    const __nv_bfloat16* __restrict__ Wth, const __nv_bfloat16* __restrict__ Wtl,
    const __nv_bfloat16* __restrict__ Xh, const __nv_bfloat16* __restrict__ Xl,
    float* __restrict__ dout,
    const float* __restrict__ gg, const float* __restrict__ bb,
    const float* __restrict__ mm, const float* __restrict__ vv,
    int M, int out_mode, int b, int m0, int n0)
{
    const unsigned sbc = smem_u32(csm);
    const int N = 4096;
    const int t = threadIdx.x, lane = t & 31, w = t >> 5;

    auto chunk_copy = [&](unsigned base, int k0) {
#pragma unroll
        for (int c = t; c < 1536; c += 128) {
            if (c < 512) {
                int arr = c >> 8, rem = c & 255, r = rem >> 3, c16 = rem & 7;
                const __nv_bfloat16* s = (arr ? Wtl : Wth) + (k0 + r) * M + m0 + c16 * 8;
                cp_async16(base + arr * BW_L + r * 144 + c16 * 16, s);
            } else {
                int c2 = c - 512;
                int arr = c2 >> 9, rem = c2 & 511, r = rem >> 4, c16 = rem & 15;
                const __nv_bfloat16* s = (arr ? Xl : Xh) + (k0 + r) * N + n0 + c16 * 8;
                cp_async16(base + BX_H + arr * (BX_L - BX_H) + r * 272 + c16 * 16, s);
            }
        }
        cp_commit();
    };

    chunk_copy(sbc, 0);

    float S[16][4];
#pragma unroll
    for (int j = 0; j < 16; j++)
#pragma unroll
        for (int c = 0; c < 4; c++) S[j][c] = 0.f;

    for (int c0 = 0; c0 < 8; c0++) {
        cp_wait_all();
        __syncthreads();
        if (c0 < 7) chunk_copy(sbc + ((c0 + 1) & 1) * BUFB, (c0 + 1) * 32);
        const unsigned bbuf = sbc + (c0 & 1) * BUFB;

        unsigned wa_[2][2][4];
#pragma unroll
        for (int sp = 0; sp < 2; sp++)
#pragma unroll
            for (int s = 0; s < 2; s++) {
                unsigned drow = s * 16 + ((lane >> 4) & 1) * 8 + (lane & 7);
                unsigned col  = (unsigned)w * 32 + ((lane >> 3) & 1) * 16;
                ldsm_x4t(wa_[sp][s][0], wa_[sp][s][1], wa_[sp][s][2], wa_[sp][s][3],
                         bbuf + sp * BW_L + drow * 144 + col);
            }
#pragma unroll
        for (int j = 0; j < 16; j++) {
            unsigned xh0, xh1, xh2, xh3, xl0, xl1, xl2, xl3;
            ldsm_x4t(xh0, xh1, xh2, xh3, bbuf + BX_H + lane * 272 + j * 16);
            ldsm_x4t(xl0, xl1, xl2, xl3, bbuf + BX_L + lane * 272 + j * 16);
            mma16816(S[j][0], S[j][1], S[j][2], S[j][3],
                     wa_[0][0][0], wa_[0][0][1], wa_[0][0][2], wa_[0][0][3], xh0, xh1);
            mma16816(S[j][0], S[j][1], S[j][2], S[j][3],
                     wa_[0][1][0], wa_[0][1][1], wa_[0][1][2], wa_[0][1][3], xh2, xh3);
            mma16816(S[j][0], S[j][1], S[j][2], S[j][3],
                     wa_[0][0][0], wa_[0][0][1], wa_[0][0][2], wa_[0][0][3], xl0, xl1);
            mma16816(S[j][0], S[j][1], S[j][2], S[j][3],
                     wa_[0][1][0], wa_[0][1][1], wa_[0][1][2], wa_[0][1][3], xl2, xl3);
            mma16816(S[j][0], S[j][1], S[j][2], S[j][3],
                     wa_[1][0][0], wa_[1][0][1], wa_[1][0][2], wa_[1][0][3], xh0, xh1);
            mma16816(S[j][0], S[j][1], S[j][2], S[j][3],
                     wa_[1][1][0], wa_[1][1][1], wa_[1][1][2], wa_[1][1][3], xh2, xh3);
        }
    }

    const int r0 = m0 + w * 16 + (lane >> 2);
    const int r1 = r0 + 8;
    float s0 = gg[r0] * rsqrtf(vv[r0] + BN_EPS);
    float bi0 = bb[r0] - mm[r0] * s0;
    float s1 = gg[r1] * rsqrtf(vv[r1] + BN_EPS);
    float bi1 = bb[r1] - mm[r1] * s1;
    if (out_mode == 0 && r0 < 256) { bi0 *= SC; }
    if (out_mode == 0 && r1 < 256) { bi1 *= SC; }

#pragma unroll
    for (int j = 0; j < 16; j++) {
        int n = n0 + j * 8 + (lane & 3) * 2;
        float o0 = S[j][0] * s0 + bi0, o1 = S[j][1] * s0 + bi0;
        float o2 = S[j][2] * s1 + bi1, o3 = S[j][3] * s1 + bi1;
        long i0 = (long)b * M * 4096 + (long)r0 * 4096 + n;
        long i1 = (long)b * M * 4096 + (long)r1 * 4096 + n;
        if (out_mode == 2) {
            *reinterpret_cast<float2*>(&dout[i0]) = make_float2(o0, o1);
            *reinterpret_cast<float2*>(&dout[i1]) = make_float2(o2, o3);
        } else {
            if (out_mode == 1) {
                *reinterpret_cast<float2*>(&g_yv[i0]) = make_float2(o0, o1);
                *reinterpret_cast<float2*>(&g_yv[i1]) = make_float2(o2, o3);
            }
            __nv_bfloat16* H = (out_mode == 0 ? g_qk_hi : g_v_hi);
            __nv_bfloat16* L = (out_mode == 0 ? g_qk_lo : g_v_lo);
            unsigned short h0 = bf_hi(o0), h1 = bf_hi(o1);
            unsigned short h2 = bf_hi(o2), h3 = bf_hi(o3);
            *reinterpret_cast<unsigned*>(&H[i0]) = pk(h0, h1);
            *reinterpret_cast<unsigned*>(&H[i1]) = pk(h2, h3);
            *reinterpret_cast<unsigned*>(&L[i0]) = pk(bf_lo(o0, h0), bf_lo(o1, h1));
            *reinterpret_cast<unsigned*>(&L[i1]) = pk(bf_lo(o2, h2), bf_lo(o3, h3));
        }
    }
}

// fused qk + v conv: blockIdx.y in [0,8) -> qk rows, [8,12) -> v rows
__global__ __launch_bounds__(128, 3) void conv_qkv_p(
    const float* __restrict__ qk_g, const float* __restrict__ qk_b,
    const float* __restrict__ qk_m, const float* __restrict__ qk_v,
    const float* __restrict__ v_g, const float* __restrict__ v_b,
    const float* __restrict__ v_m, const float* __restrict__ v_v)
{
    extern __shared__ char csm[];
    const int b = blockIdx.z, n0 = blockIdx.x * 128;
    const __nv_bfloat16* Xh = g_xh + b * 256 * 4096;
    const __nv_bfloat16* Xl = g_xl + b * 256 * 4096;
    if (blockIdx.y < 8)
        conv_core(csm, g_wqkt_h, g_wqkt_l, Xh, Xl, nullptr,
                  qk_g, qk_b, qk_m, qk_v, 512, 0, b, blockIdx.y * 64, n0);
    else
        conv_core(csm, g_wvt_h, g_wvt_l, Xh, Xl, nullptr,
                  v_g, v_b, v_m, v_v, 256, 1, b, (blockIdx.y - 8) * 64, n0);
}

__global__ __launch_bounds__(128, 3) void conv_proj(
    float* __restrict__ dout,
    const float* __restrict__ pr_g, const float* __restrict__ pr_b,
    const float* __restrict__ pr_m, const float* __restrict__ pr_v)
{
    extern __shared__ char csm[];
    const int b = blockIdx.z, n0 = blockIdx.x * 128;
    conv_core(csm, g_wprt_h, g_wprt_l,
              g_oph + b * 256 * 4096, g_opl + b * 256 * 4096, dout,
              pr_g, pr_b, pr_m, pr_v, 256, 2, b, blockIdx.y * 64, n0);
}

// ---------------- depthwise 5x5 (pad 2) + BN, vectorized (R15 version) --------
__global__ __launch_bounds__(256) void dw5_bn(
    const float* __restrict__ w_pe,
    const float* __restrict__ gg, const float* __restrict__ bb,
    const float* __restrict__ mm, const float* __restrict__ vv)
{
    const int bc = blockIdx.x;
    const int c  = bc & 255;
    const float* src = g_yv + bc * 4096;
    float* dst = g_pp + bc * 4096;

    __shared__ float tile[68][68];
    __shared__ float wk[25];
    const int t = threadIdx.x;

    for (int i = t * 4; i < 68 * 68; i += 1024)
        *reinterpret_cast<float4*>(&((float*)tile)[i]) = make_float4(0.f, 0.f, 0.f, 0.f);
    if (t < 25) wk[t] = w_pe[c * 25 + t];
    __syncthreads();
    for (int i = t * 4; i < 4096; i += 1024) {
        float4 v = *reinterpret_cast<const float4*>(&src[i]);
        int y = (i >> 6) + 2, x = (i & 63) + 2;
        tile[y][x] = v.x; tile[y][x + 1] = v.y; tile[y][x + 2] = v.z; tile[y][x + 3] = v.w;
    }
    __syncthreads();

    float s  = gg[c] * rsqrtf(vv[c] + BN_EPS);
    float bi = bb[c] - mm[c] * s;

    for (int i = t * 4; i < 4096; i += 1024) {
        int y = i >> 6, x = i & 63;
        float a0 = 0.f, a1 = 0.f, a2 = 0.f, a3 = 0.f;
#pragma unroll
        for (int ky = 0; ky < 5; ky++)
#pragma unroll
            for (int kx = 0; kx < 5; kx++) {
                float wv = wk[ky * 5 + kx];
                a0 = fmaf(tile[y + ky][x + kx],     wv, a0);
                a1 = fmaf(tile[y + ky][x + kx + 1], wv, a1);
                a2 = fmaf(tile[y + ky][x + kx + 2], wv, a2);
                a3 = fmaf(tile[y + ky][x + kx + 3], wv, a3);
            }
        *reinterpret_cast<float4*>(&dst[i]) =
            make_float4(a0 * s + bi, a1 * s + bi, a2 * s + bi, a3 * s + bi);
    }
}

// ================= flash attention (unchanged from R14/R15 WIN) ===============
#define TS 272
#define BUFSZ  34816
#define FM_SMEM (2 * BUFSZ)

__device__ __forceinline__ void kv_copy(unsigned base, int t,
    const __nv_bfloat16* Kh, const __nv_bfloat16* Kl,
    const __nv_bfloat16* Vh, const __nv_bfloat16* Vl, int m0)
{
#pragma unroll
    for (int c = t; c < 2048; c += 128) {
        int arr = c >> 9, d = (c >> 4) & 31, mb = c & 15;
        const __nv_bfloat16* s =
            (arr == 0 ? Kh : (arr == 1 ? Kl : (arr == 2 ? Vh : Vl))) + d * 4096 + m0 + mb * 8;
        cp_async16(base + arr * 8704 + d * TS + mb * 16, s);
    }
    cp_commit();
}

__global__ __launch_bounds__(128, 3) void flash_mma()
{
    extern __shared__ char smbuf[];
    const unsigned sb = smem_u32(smbuf);
    const int t = threadIdx.x, lane = t & 31, w = t >> 5;

    const int bh = blockIdx.y;
    const int b = bh >> 5, area = (bh >> 3) & 3, h = bh & 7;
    const int q0 = blockIdx.x * 64;

    const int qch = (b * 512 + h * 32) * 4096 + area * 1024;
    const int kch = (b * 512 + 256 + h * 32) * 4096 + area * 1024;
    const int vch = (b * 256 + h * 32) * 4096 + area * 1024;
    const __nv_bfloat16* Qh = g_qk_hi + qch + q0;
    const __nv_bfloat16* Ql = g_qk_lo + qch + q0;
    const __nv_bfloat16* Kh = g_qk_hi + kch;
    const __nv_bfloat16* Kl = g_qk_lo + kch;
    const __nv_bfloat16* Vh = g_v_hi + vch;
    const __nv_bfloat16* Vl = g_v_lo + vch;

#pragma unroll
    for (int c = t; c < 512; c += 128) {
        int arr = c >> 8, d = (c >> 3) & 31, qb = c & 7;
        const __nv_bfloat16* s = (arr ? Ql : Qh) + d * 4096 + qb * 8;
        *reinterpret_cast<uint4*>(smbuf + arr * 8704 + d * TS + qb * 16) =
            *reinterpret_cast<const uint4*>(s);
    }
    __syncthreads();

    unsigned qa[2][2][4];
#pragma unroll
    for (int sp = 0; sp < 2; sp++)
#pragma unroll
        for (int s = 0; s < 2; s++) {
            unsigned drow = s * 16 + ((lane >> 4) & 1) * 8 + (lane & 7);
            unsigned col  = (unsigned)w * 32 + ((lane >> 3) & 1) * 16;
            ldsm_x4t(qa[sp][s][0], qa[sp][s][1], qa[sp][s][2], qa[sp][s][3],
                     sb + sp * 8704 + drow * TS + col);
        }
    __syncthreads();

    kv_copy(sb, t, Kh, Kl, Vh, Vl, 0);

    float Oacc[4][4];
#pragma unroll
    for (int dn = 0; dn < 4; dn++)
#pragma unroll
        for (int c = 0; c < 4; c++) Oacc[dn][c] = 0.f;
    float mr0 = -1e30f, mr1 = -1e30f, lr0 = 0.f, lr1 = 0.f;

    for (int kt = 0; kt < 8; kt++) {
        cp_wait_all();
        __syncthreads();
        if (kt < 7)
            kv_copy(sb + ((kt + 1) & 1) * BUFSZ, t, Kh, Kl, Vh, Vl, (kt + 1) * 128);
        const unsigned kb = sb + (kt & 1) * BUFSZ;

        float S[16][4];
#pragma unroll
        for (int j = 0; j < 16; j++) {
            unsigned kh0, kh1, kh2, kh3, kl0, kl1, kl2, kl3;
            ldsm_x4t(kh0, kh1, kh2, kh3, kb + lane * TS + j * 16);
            ldsm_x4t(kl0, kl1, kl2, kl3, kb + 8704 + lane * TS + j * 16);
            float a0 = 0.f, a1 = 0.f, a2 = 0.f, a3 = 0.f;
            float b0 = 0.f, b1 = 0.f, b2 = 0.f, b3 = 0.f;
            mma16816(a0, a1, a2, a3, qa[0][0][0], qa[0][0][1], qa[0][0][2], qa[0][0][3], kh0, kh1);
            mma16816(a0, a1, a2, a3, qa[0][1][0], qa[0][1][1], qa[0][1][2], qa[0][1][3], kh2, kh3);
            mma16816(b0, b1, b2, b3, qa[0][0][0], qa[0][0][1], qa[0][0][2], qa[0][0][3], kl0, kl1);
            mma16816(b0, b1, b2, b3, qa[0][1][0], qa[0][1][1], qa[0][1][2], qa[0][1][3], kl2, kl3);
            mma16816(b0, b1, b2, b3, qa[1][0][0], qa[1][0][1], qa[1][0][2], qa[1][0][3], kh0, kh1);
            mma16816(b0, b1, b2, b3, qa[1][1][0], qa[1][1][1], qa[1][1][2], qa[1][1][3], kh2, kh3);
            S[j][0] = a0 + b0; S[j][1] = a1 + b1; S[j][2] = a2 + b2; S[j][3] = a3 + b3;
        }

        float mx0 = -1e30f, mx1 = -1e30f;
#pragma unroll
        for (int j = 0; j < 16; j++) {
            mx0 = fmaxf(mx0, fmaxf(S[j][0], S[j][1]));
            mx1 = fmaxf(mx1, fmaxf(S[j][2], S[j][3]));
        }
        mx0 = fmaxf(mx0, __shfl_xor_sync(0xFFFFFFFFu, mx0, 1));
        mx0 = fmaxf(mx0, __shfl_xor_sync(0xFFFFFFFFu, mx0, 2));
        mx1 = fmaxf(mx1, __shfl_xor_sync(0xFFFFFFFFu, mx1, 1));
        mx1 = fmaxf(mx1, __shfl_xor_sync(0xFFFFFFFFu, mx1, 2));
        float nm0 = fmaxf(mr0, mx0), nm1 = fmaxf(mr1, mx1);
        float be0 = __expf(mr0 - nm0), be1 = __expf(mr1 - nm1);
        float lt0 = 0.f, lt1 = 0.f;
#pragma unroll
        for (int j = 0; j < 16; j++) {
            S[j][0] = __expf(S[j][0] - nm0); lt0 += S[j][0];
            S[j][1] = __expf(S[j][1] - nm0); lt0 += S[j][1];
            S[j][2] = __expf(S[j][2] - nm1); lt1 += S[j][2];
            S[j][3] = __expf(S[j][3] - nm1); lt1 += S[j][3];
        }
        lt0 += __shfl_xor_sync(0xFFFFFFFFu, lt0, 1);
        lt0 += __shfl_xor_sync(0xFFFFFFFFu, lt0, 2);
        lt1 += __shfl_xor_sync(0xFFFFFFFFu, lt1, 1);
        lt1 += __shfl_xor_sync(0xFFFFFFFFu, lt1, 2);
        lr0 = lr0 * be0 + lt0; lr1 = lr1 * be1 + lt1;
        mr0 = nm0; mr1 = nm1;
#pragma unroll
        for (int dn = 0; dn < 4; dn++) {
            Oacc[dn][0] *= be0; Oacc[dn][1] *= be0;
            Oacc[dn][2] *= be1; Oacc[dn][3] *= be1;
        }

#pragma unroll
        for (int tt = 0; tt < 8; tt++) {
            unsigned ah[4], al[4];
            {
                unsigned short h0 = bf_hi(S[2*tt][0]),   h1 = bf_hi(S[2*tt][1]);
                unsigned short h2 = bf_hi(S[2*tt][2]),   h3 = bf_hi(S[2*tt][3]);
                unsigned short h4 = bf_hi(S[2*tt+1][0]), h5 = bf_hi(S[2*tt+1][1]);
                unsigned short h6 = bf_hi(S[2*tt+1][2]), h7 = bf_hi(S[2*tt+1][3]);
                ah[0] = pk(h0, h1); ah[1] = pk(h2, h3);
                ah[2] = pk(h4, h5); ah[3] = pk(h6, h7);
                al[0] = pk(bf_lo(S[2*tt][0], h0),   bf_lo(S[2*tt][1], h1));
                al[1] = pk(bf_lo(S[2*tt][2], h2),   bf_lo(S[2*tt][3], h3));
                al[2] = pk(bf_lo(S[2*tt+1][0], h4), bf_lo(S[2*tt+1][1], h5));
                al[3] = pk(bf_lo(S[2*tt+1][2], h6), bf_lo(S[2*tt+1][3], h7));
            }
#pragma unroll
            for (int p = 0; p < 2; p++) {
                unsigned drow = (unsigned)p * 16 + ((lane >> 4) & 1) * 8 + (lane & 7);
                unsigned colb = (unsigned)tt * 32 + ((lane >> 3) & 1) * 16;
                unsigned vh0, vh1, vh2, vh3, vl0, vl1, vl2, vl3;
                ldsm_x4(vh0, vh1, vh2, vh3, kb + 17408 + drow * TS + colb);
                ldsm_x4(vl0, vl1, vl2, vl3, kb + 26112 + drow * TS + colb);
                int d0 = p * 2, d1 = p * 2 + 1;
                mma16816(Oacc[d0][0], Oacc[d0][1], Oacc[d0][2], Oacc[d0][3],
                         ah[0], ah[1], ah[2], ah[3], vh0, vh1);
                mma16816(Oacc[d0][0], Oacc[d0][1], Oacc[d0][2], Oacc[d0][3],
                         ah[0], ah[1], ah[2], ah[3], vl0, vl1);
                mma16816(Oacc[d0][0], Oacc[d0][1], Oacc[d0][2], Oacc[d0][3],
                         al[0], al[1], al[2], al[3], vh0, vh1);
                mma16816(Oacc[d1][0], Oacc[d1][1], Oacc[d1][2], Oacc[d1][3],
                         ah[0], ah[1], ah[2], ah[3], vh2, vh3);
                mma16816(Oacc[d1][0], Oacc[d1][1], Oacc[d1][2], Oacc[d1][3],
                         ah[0], ah[1], ah[2], ah[3], vl2, vl3);
                mma16816(Oacc[d1][0], Oacc[d1][1], Oacc[d1][2], Oacc[d1][3],
                         al[0], al[1], al[2], al[3], vh2, vh3);
            }
        }
    }

    __syncthreads();
    {
        float inv0 = 1.f / lr0, inv1 = 1.f / lr1;
        int r = w * 16 + (lane >> 2);
        int dc = (lane & 3) * 2;
        float* Os = (float*)(smbuf);
#pragma unroll
        for (int dn = 0; dn < 4; dn++) {
            int d = dn * 8 + dc;
            Os[r * 33 + d]           = Oacc[dn][0] * inv0;
            Os[r * 33 + d + 1]       = Oacc[dn][1] * inv0;
            Os[(r + 8) * 33 + d]     = Oacc[dn][2] * inv1;
            Os[(r + 8) * 33 + d + 1] = Oacc[dn][3] * inv1;
        }
    }
    __syncthreads();

    const long ob = (long)(b * 256 + h * 32) * 4096 + area * 1024 + q0;
    const float* Pp = g_pp + ob;
    __nv_bfloat16* OH = g_oph + ob;
    __nv_bfloat16* OL = g_opl + ob;
    const float* Os = (const float*)(smbuf);
    for (int i = t * 4; i < 2048; i += 512) {
        int d = i >> 6, q = i & 63;
        float o[4];
        o[0] = Os[(q + 0) * 33 + d];
        o[1] = Os[(q + 1) * 33 + d];
        o[2] = Os[(q + 2) * 33 + d];
        o[3] = Os[(q + 3) * 33 + d];
        float4 p = *reinterpret_cast<const float4*>(&Pp[d * 4096 + q]);
        o[0] += p.x; o[1] += p.y; o[2] += p.z; o[3] += p.w;
        unsigned short hh[4], ll[4];
#pragma unroll
        for (int j = 0; j < 4; j++) { hh[j] = bf_hi(o[j]); ll[j] = bf_lo(o[j], hh[j]); }
        *reinterpret_cast<uint2*>(&OH[d * 4096 + q]) =
            make_uint2(pk(hh[0], hh[1]), pk(hh[2], hh[3]));
        *reinterpret_cast<uint2*>(&OL[d * 4096 + q]) =
            make_uint2(pk(ll[0], ll[1]), pk(ll[2], ll[3]));
    }
}

// ---------------- launch ------------------------------------------------------
extern "C" void kernel_launch(void* const* d_in, const int* in_sizes, int n_in,
                              void* d_out, int out_size)
{
    const float *x, *w_qk, *w_v, *w_pe, *w_proj;
    const float *qk_g, *qk_b, *qk_m, *qk_v;
    const float *v_g, *v_b, *v_m, *v_v;
    const float *pe_g, *pe_b, *pe_m, *pe_v;
    const float *pr_g, *pr_b, *pr_m, *pr_v;

    x = (const float*)d_in[0];
    w_qk = (const float*)d_in[1];
    if (in_sizes[2] == 512) {
        qk_g = (const float*)d_in[2];  qk_b = (const float*)d_in[3];
        qk_m = (const float*)d_in[4];  qk_v = (const float*)d_in[5];
        w_v  = (const float*)d_in[6];
        v_g  = (const float*)d_in[7];  v_b  = (const float*)d_in[8];
        v_m  = (const float*)d_in[9];  v_v  = (const float*)d_in[10];
        w_pe = (const float*)d_in[11];
        pe_g = (const float*)d_in[12]; pe_b = (const float*)d_in[13];
        pe_m = (const float*)d_in[14]; pe_v = (const float*)d_in[15];
        w_proj = (const float*)d_in[16];
        pr_g = (const float*)d_in[17]; pr_b = (const float*)d_in[18];
        pr_m = (const float*)d_in[19]; pr_v = (const float*)d_in[20];
    } else {
        w_v    = (const float*)d_in[2];
        w_pe   = (const float*)d_in[3];
        w_proj = (const float*)d_in[4];
        qk_g = (const float*)d_in[5];  qk_b = (const float*)d_in[6];
        qk_m = (const float*)d_in[7];  qk_v = (const float*)d_in[8];
        v_g  = (const float*)d_in[9];  v_b  = (const float*)d_in[10];
        v_m  = (const float*)d_in[11]; v_v  = (const float*)d_in[12];
        pe_g = (const float*)d_in[13]; pe_b = (const float*)d_in[14];
        pe_m = (const float*)d_in[15]; pe_v = (const float*)d_in[16];
        pr_g = (const float*)d_in[17]; pr_b = (const float*)d_in[18];
        pr_m = (const float*)d_in[19]; pr_v = (const float*)d_in[20];
    }
    float* out = (float*)d_out;

    cudaFuncSetAttribute(flash_mma, cudaFuncAttributeMaxDynamicSharedMemorySize, FM_SMEM);
    cudaFuncSetAttribute(conv_qkv_p, cudaFuncAttributeMaxDynamicSharedMemorySize, CB_SMEM);
    cudaFuncSetAttribute(conv_proj, cudaFuncAttributeMaxDynamicSharedMemorySize, CB_SMEM);

    // fused prep: all weights + x split in one launch
    prep_all<<<2048, 256>>>(w_qk, w_v, w_proj, x);

    // fused qk + v conv (12 m-jobs)
    conv_qkv_p<<<dim3(32, 12, 2), 128, CB_SMEM>>>(qk_g, qk_b, qk_m, qk_v,
                                                  v_g, v_b, v_m, v_v);
    dw5_bn<<<512, 256>>>(w_pe, pe_g, pe_b, pe_m, pe_v);
    flash_mma<<<dim3(16, 64), 128, FM_SMEM>>>();
    conv_proj<<<dim3(32, 4, 2), 128, CB_SMEM>>>(out, pr_g, pr_b, pr_m, pr_v);
}